// round 16
// baseline (speedup 1.0000x reference)
#include <cuda_runtime.h>
#include <cuda_fp16.h>

#define CCH 256        // channels (all levels)
#define NIMG 2         // batch
#define NBINS 49       // 7*7
#define SPITCH_H 264   // staging pitch in HALVES (=528B, 16B-aligned per bin row)

// NHWC fp16 scratch for all 4 levels (element offsets):
// L0 @ 0, L1 @ 33,554,432, L2 @ 41,943,040, L3 @ 44,040,192 (89 MB total)
__device__ __half g_nhwc[44564480];

__constant__ long long c_lvl_off[4] = {0LL, 33554432LL, 41943040LL, 44040192LL};

// ---------------------------------------------------------------------------
// Fused NCHW(fp32) -> NHWC(fp16) transpose, 4 hw-subtiles per CTA (MLP=4).
// blockIdx.x: L0 [0,512), L1 [512,640), L2 [640,672), L3 [672,680).
// blockIdx.y = channel tile (8), blockIdx.z = image (2). Block (8,32).
// (R8 version — measured ~6.1 TB/s effective, at the streaming cap.)
// ---------------------------------------------------------------------------
__global__ __launch_bounds__(256) void transpose_fused(
    const float* __restrict__ f0, const float* __restrict__ f1,
    const float* __restrict__ f2, const float* __restrict__ f3)
{
    __shared__ float tile[4][32][33];              // 16,896 B

    const int bx = blockIdx.x;
    int lvl, tb;
    const float* src;
    if (bx < 512)      { lvl = 0; tb = bx;       src = f0; }
    else if (bx < 640) { lvl = 1; tb = bx - 512; src = f1; }
    else if (bx < 672) { lvl = 2; tb = bx - 640; src = f2; }
    else               { lvl = 3; tb = bx - 672; src = f3; }

    const int HW  = (256 >> lvl) * (256 >> lvl);
    const int hw0 = tb * 128;
    const int c0  = blockIdx.y * 32;
    const int n   = blockIdx.z;
    const int tx  = threadIdx.x;   // 0..7
    const int ty  = threadIdx.y;   // 0..31

    const float* s = src + (size_t)n * CCH * HW + (size_t)(c0 + ty) * HW + hw0 + tx * 4;

#pragma unroll
    for (int j = 0; j < 4; ++j) {
        const float4 v = *reinterpret_cast<const float4*>(s + j * 32);
        tile[j][ty][tx * 4 + 0] = v.x;
        tile[j][ty][tx * 4 + 1] = v.y;
        tile[j][ty][tx * 4 + 2] = v.z;
        tile[j][ty][tx * 4 + 3] = v.w;
    }
    __syncthreads();

    __half* dst = g_nhwc + c_lvl_off[lvl] + (size_t)n * HW * CCH
                + (size_t)(hw0 + ty) * CCH + c0 + tx * 4;

#pragma unroll
    for (int j = 0; j < 4; ++j) {
        const __half2 a = __floats2half2_rn(tile[j][tx * 4 + 0][ty], tile[j][tx * 4 + 1][ty]);
        const __half2 b = __floats2half2_rn(tile[j][tx * 4 + 2][ty], tile[j][tx * 4 + 3][ty]);
        uint2 o;
        o.x = *reinterpret_cast<const unsigned int*>(&a);
        o.y = *reinterpret_cast<const unsigned int*>(&b);
        *reinterpret_cast<uint2*>(dst + (size_t)j * 32 * CCH) = o;
    }
}

// ---------------------------------------------------------------------------
// ROIAlign pooler over fp16 NHWC scratch — R8 structure. TWO CTAs per box
// (phase 0: bins [0,25), phase 1: [25,49)). 256 threads: q = tid&31 ->
// channel oct (uint4 of 8 halves), coalesced; bs = tid>>5 -> one bin per warp
// iteration, all 16 taps straight-line unrolled (MLP 16). Per-bin tap table
// uint2 {offset, half2 w*0.25} -> LDS.64 broadcast. fp16 intra-sample
// bilinear, per-sample fp32 convert, fp32 bin accumulation.
// R16 deltas vs R8: staging buffer in fp16 (halves staging STS/LDS bytes;
// smem 30 -> ~17 KB) and __launch_bounds__(256,7) (36-reg target, 7 CTAs/SM).
// ---------------------------------------------------------------------------
__global__ __launch_bounds__(256, 7) void roi_pool_kernel(
    const float* __restrict__ boxes, float* __restrict__ out, int R)
{
    __shared__ __half s_out[25 * SPITCH_H];        // 13,200 B
    __shared__ uint2  s_tap[25 * 16];              //  3,200 B {offset, half2 w}
    __shared__ int    s_i0[2][14], s_i1[2][14];
    __shared__ float  s_h[2][14],  s_l[2][14];

    const int bid   = blockIdx.x;
    const int m     = bid >> 1;
    const int phase = bid & 1;
    const int tid   = threadIdx.x;

    const int b0   = phase ? 25 : 0;
    const int bcnt = phase ? 24 : 25;

    const float bx1 = __ldg(boxes + 4 * m + 0);
    const float by1 = __ldg(boxes + 4 * m + 1);
    const float bx2 = __ldg(boxes + 4 * m + 2);
    const float by2 = __ldg(boxes + 4 * m + 3);

    const float area = fmaxf((bx2 - bx1) * (by2 - by1), 0.0f);
    const float sz   = sqrtf(area);
    int lvl = (int)floorf(4.0f + log2f(sz / 224.0f + 1e-8f));
    lvl = min(max(lvl, 2), 5) - 2;                 // 0..3

    const int   Hd    = 256 >> lvl;
    const int   Wd    = Hd;
    const float scale = 0.25f / (float)(1 << lvl);
    const int   n     = m / R;

    const __half* fbase = g_nhwc + c_lvl_off[lvl] + (size_t)n * Hd * Wd * CCH;

    if (tid < 28) {
        const int axis = tid / 14;                 // 0 = x, 1 = y
        const int k    = tid - axis * 14;
        const float c1 = axis ? by1 : bx1;
        const float c2 = axis ? by2 : bx2;
        const int  lim = Hd;
        const float start = c1 * scale - 0.5f;
        const float bsz   = (c2 * scale - 0.5f - start) * (1.0f / 7.0f);
        const float off   = (float)(k >> 1) + ((k & 1) ? 0.75f : 0.25f);
        const float t     = start + off * bsz;
        const bool  v     = (t >= -1.0f) && (t <= (float)lim);
        const float tc    = fminf(fmaxf(t, 0.0f), (float)(lim - 1));
        const int   i0    = (int)tc;
        const int   i1    = min(i0 + 1, lim - 1);
        const float l     = tc - (float)i0;
        s_i0[axis][k] = i0;
        s_i1[axis][k] = i1;
        s_l[axis][k]  = v ? l : 0.0f;
        s_h[axis][k]  = v ? (1.0f - l) : 0.0f;
    }
    __syncthreads();

    // Per-phase tap table: i -> local bin i>>4, tap i&15 ([3]=sy,[2]=sx,[1]=cy,[0]=cx).
    for (int i = tid; i < bcnt * 16; i += 256) {
        const int bin = b0 + (i >> 4);
        const int t   = i & 15;
        const int py  = bin / 7;
        const int px  = bin - py * 7;
        const int iy  = py * 2 + (t >> 3);
        const int ix  = px * 2 + ((t >> 2) & 1);
        const int cy  = (t >> 1) & 1;
        const int cx  = t & 1;
        const int   yy = cy ? s_i1[1][iy] : s_i0[1][iy];
        const int   xx = cx ? s_i1[0][ix] : s_i0[0][ix];
        const float wy = cy ? s_l[1][iy]  : s_h[1][iy];
        const float wx = cx ? s_l[0][ix]  : s_h[0][ix];
        const __half2 w = __float2half2_rn(wy * wx * 0.25f);
        uint2 e;
        e.x = (unsigned int)(yy * Wd + xx);
        e.y = *reinterpret_cast<const unsigned int*>(&w);
        s_tap[i] = e;
    }
    __syncthreads();

    const int q  = tid & 31;
    const int bs = tid >> 5;
    const uint4* base16 = reinterpret_cast<const uint4*>(fbase) + q;
    float* outm = out + (size_t)m * (NBINS * CCH);

    for (int bb = bs; bb < bcnt; bb += 8) {
        const int tb = bb * 16;
        float2 facc[4] = {{0.f,0.f},{0.f,0.f},{0.f,0.f},{0.f,0.f}};
#pragma unroll
        for (int smp = 0; smp < 4; ++smp) {
            __half2 hacc[4];
#pragma unroll
            for (int t = 0; t < 4; ++t) {
                const uint2 e = s_tap[tb + smp * 4 + t];   // LDS.64 broadcast
                const __half2 w = *reinterpret_cast<const __half2*>(&e.y);
                const uint4 u = __ldg(base16 + (size_t)e.x * 32);
                const __half2* h = reinterpret_cast<const __half2*>(&u);
#pragma unroll
                for (int j = 0; j < 4; ++j)
                    hacc[j] = (t == 0) ? __hmul2(h[j], w)
                                       : __hfma2(h[j], w, hacc[j]);
            }
#pragma unroll
            for (int j = 0; j < 4; ++j) {
                const float2 f = __half22float2(hacc[j]);
                facc[j].x += f.x;
                facc[j].y += f.y;
            }
        }
        // stage as fp16: 8 halves (uint4) per lane, one STS.128
        uint4 pk;
        {
            const __half2 p0 = __floats2half2_rn(facc[0].x, facc[0].y);
            const __half2 p1 = __floats2half2_rn(facc[1].x, facc[1].y);
            const __half2 p2 = __floats2half2_rn(facc[2].x, facc[2].y);
            const __half2 p3 = __floats2half2_rn(facc[3].x, facc[3].y);
            pk.x = *reinterpret_cast<const unsigned int*>(&p0);
            pk.y = *reinterpret_cast<const unsigned int*>(&p1);
            pk.z = *reinterpret_cast<const unsigned int*>(&p2);
            pk.w = *reinterpret_cast<const unsigned int*>(&p3);
        }
        *reinterpret_cast<uint4*>(s_out + bb * SPITCH_H + q * 8) = pk;
    }
    __syncthreads();

    // Transposed dump: compile-time bin counts (magic-multiply div).
    if (phase == 0) {
        for (int i = tid; i < 25 * CCH; i += 256) {
            const int c  = i / 25;
            const int bb = i - c * 25;
            outm[c * NBINS + bb] = __half2float(s_out[bb * SPITCH_H + c]);
        }
    } else {
        for (int i = tid; i < 24 * CCH; i += 256) {
            const int c  = i / 24;
            const int bb = i - c * 24;
            outm[c * NBINS + 25 + bb] = __half2float(s_out[bb * SPITCH_H + c]);
        }
    }
}

// ---------------------------------------------------------------------------
extern "C" void kernel_launch(void* const* d_in, const int* in_sizes, int n_in,
                              void* d_out, int out_size)
{
    const float* f0    = (const float*)d_in[0];
    const float* f1    = (const float*)d_in[1];
    const float* f2    = (const float*)d_in[2];
    const float* f3    = (const float*)d_in[3];
    const float* boxes = (const float*)d_in[4];
    float*       out   = (float*)d_out;

    const int M = in_sizes[4] / 4;   // 1024 boxes
    const int R = M / NIMG;          // 512 per image

    transpose_fused<<<dim3(680, CCH / 32, NIMG), dim3(8, 32)>>>(f0, f1, f2, f3);
    roi_pool_kernel<<<M * 2, 256>>>(boxes, out, R);
}

// round 17
// speedup vs baseline: 1.3690x; 1.3690x over previous
#include <cuda_runtime.h>
#include <cuda_fp16.h>

#define CCH 256        // channels (all levels)
#define NIMG 2         // batch
#define NBINS 49       // 7*7
#define SPITCH_H 264   // staging pitch in HALVES (=528B, 16B-aligned per bin row)

// NHWC fp16 scratch for all 4 levels (element offsets):
// L0 @ 0, L1 @ 33,554,432, L2 @ 41,943,040, L3 @ 44,040,192 (89 MB total)
__device__ __half g_nhwc[44564480];

__constant__ long long c_lvl_off[4] = {0LL, 33554432LL, 41943040LL, 44040192LL};

// ---------------------------------------------------------------------------
// Fused NCHW(fp32) -> NHWC(fp16) transpose, 4 hw-subtiles per CTA (MLP=4).
// blockIdx.x: L0 [0,512), L1 [512,640), L2 [640,672), L3 [672,680).
// blockIdx.y = channel tile (8), blockIdx.z = image (2). Block (8,32).
// (R8 version — measured ~6.1 TB/s effective, at the streaming cap.)
// ---------------------------------------------------------------------------
__global__ __launch_bounds__(256) void transpose_fused(
    const float* __restrict__ f0, const float* __restrict__ f1,
    const float* __restrict__ f2, const float* __restrict__ f3)
{
    __shared__ float tile[4][32][33];              // 16,896 B

    const int bx = blockIdx.x;
    int lvl, tb;
    const float* src;
    if (bx < 512)      { lvl = 0; tb = bx;       src = f0; }
    else if (bx < 640) { lvl = 1; tb = bx - 512; src = f1; }
    else if (bx < 672) { lvl = 2; tb = bx - 640; src = f2; }
    else               { lvl = 3; tb = bx - 672; src = f3; }

    const int HW  = (256 >> lvl) * (256 >> lvl);
    const int hw0 = tb * 128;
    const int c0  = blockIdx.y * 32;
    const int n   = blockIdx.z;
    const int tx  = threadIdx.x;   // 0..7
    const int ty  = threadIdx.y;   // 0..31

    const float* s = src + (size_t)n * CCH * HW + (size_t)(c0 + ty) * HW + hw0 + tx * 4;

#pragma unroll
    for (int j = 0; j < 4; ++j) {
        const float4 v = *reinterpret_cast<const float4*>(s + j * 32);
        tile[j][ty][tx * 4 + 0] = v.x;
        tile[j][ty][tx * 4 + 1] = v.y;
        tile[j][ty][tx * 4 + 2] = v.z;
        tile[j][ty][tx * 4 + 3] = v.w;
    }
    __syncthreads();

    __half* dst = g_nhwc + c_lvl_off[lvl] + (size_t)n * HW * CCH
                + (size_t)(hw0 + ty) * CCH + c0 + tx * 4;

#pragma unroll
    for (int j = 0; j < 4; ++j) {
        const __half2 a = __floats2half2_rn(tile[j][tx * 4 + 0][ty], tile[j][tx * 4 + 1][ty]);
        const __half2 b = __floats2half2_rn(tile[j][tx * 4 + 2][ty], tile[j][tx * 4 + 3][ty]);
        uint2 o;
        o.x = *reinterpret_cast<const unsigned int*>(&a);
        o.y = *reinterpret_cast<const unsigned int*>(&b);
        *reinterpret_cast<uint2*>(dst + (size_t)j * 32 * CCH) = o;
    }
}

// ---------------------------------------------------------------------------
// ROIAlign pooler over fp16 NHWC scratch — R8 structure, natural regalloc
// (NO launch-bounds occupancy floor: the 16-tap straight-line body needs its
// ~42 registers; caps at 32 spilled and regressed in R13/R16). TWO CTAs per
// box (phase 0: bins [0,25), phase 1: [25,49)). 256 threads: q = tid&31 ->
// channel oct (uint4 of 8 halves), coalesced; bs = tid>>5 -> one bin per warp
// iteration, all 16 taps unrolled (MLP 16). Per-bin tap table uint2
// {offset, half2 w*0.25} -> LDS.64 broadcast. fp16 intra-sample bilinear,
// per-sample fp32 convert, fp32 bin accumulation.
// R17 delta vs R8: staging buffer fp16 (halves staging STS/LDS bytes,
// smem 30 -> 16.4 KB); dump converts half->float per element.
// ---------------------------------------------------------------------------
__global__ __launch_bounds__(256) void roi_pool_kernel(
    const float* __restrict__ boxes, float* __restrict__ out, int R)
{
    __shared__ __half s_out[25 * SPITCH_H];        // 13,200 B
    __shared__ uint2  s_tap[25 * 16];              //  3,200 B {offset, half2 w}
    __shared__ int    s_i0[2][14], s_i1[2][14];
    __shared__ float  s_h[2][14],  s_l[2][14];

    const int bid   = blockIdx.x;
    const int m     = bid >> 1;
    const int phase = bid & 1;
    const int tid   = threadIdx.x;

    const int b0   = phase ? 25 : 0;
    const int bcnt = phase ? 24 : 25;

    const float bx1 = __ldg(boxes + 4 * m + 0);
    const float by1 = __ldg(boxes + 4 * m + 1);
    const float bx2 = __ldg(boxes + 4 * m + 2);
    const float by2 = __ldg(boxes + 4 * m + 3);

    const float area = fmaxf((bx2 - bx1) * (by2 - by1), 0.0f);
    const float sz   = sqrtf(area);
    int lvl = (int)floorf(4.0f + log2f(sz / 224.0f + 1e-8f));
    lvl = min(max(lvl, 2), 5) - 2;                 // 0..3

    const int   Hd    = 256 >> lvl;
    const int   Wd    = Hd;
    const float scale = 0.25f / (float)(1 << lvl);
    const int   n     = m / R;

    const __half* fbase = g_nhwc + c_lvl_off[lvl] + (size_t)n * Hd * Wd * CCH;

    if (tid < 28) {
        const int axis = tid / 14;                 // 0 = x, 1 = y
        const int k    = tid - axis * 14;
        const float c1 = axis ? by1 : bx1;
        const float c2 = axis ? by2 : bx2;
        const int  lim = Hd;
        const float start = c1 * scale - 0.5f;
        const float bsz   = (c2 * scale - 0.5f - start) * (1.0f / 7.0f);
        const float off   = (float)(k >> 1) + ((k & 1) ? 0.75f : 0.25f);
        const float t     = start + off * bsz;
        const bool  v     = (t >= -1.0f) && (t <= (float)lim);
        const float tc    = fminf(fmaxf(t, 0.0f), (float)(lim - 1));
        const int   i0    = (int)tc;
        const int   i1    = min(i0 + 1, lim - 1);
        const float l     = tc - (float)i0;
        s_i0[axis][k] = i0;
        s_i1[axis][k] = i1;
        s_l[axis][k]  = v ? l : 0.0f;
        s_h[axis][k]  = v ? (1.0f - l) : 0.0f;
    }
    __syncthreads();

    // Per-phase tap table: i -> local bin i>>4, tap i&15 ([3]=sy,[2]=sx,[1]=cy,[0]=cx).
    for (int i = tid; i < bcnt * 16; i += 256) {
        const int bin = b0 + (i >> 4);
        const int t   = i & 15;
        const int py  = bin / 7;
        const int px  = bin - py * 7;
        const int iy  = py * 2 + (t >> 3);
        const int ix  = px * 2 + ((t >> 2) & 1);
        const int cy  = (t >> 1) & 1;
        const int cx  = t & 1;
        const int   yy = cy ? s_i1[1][iy] : s_i0[1][iy];
        const int   xx = cx ? s_i1[0][ix] : s_i0[0][ix];
        const float wy = cy ? s_l[1][iy]  : s_h[1][iy];
        const float wx = cx ? s_l[0][ix]  : s_h[0][ix];
        const __half2 w = __float2half2_rn(wy * wx * 0.25f);
        uint2 e;
        e.x = (unsigned int)(yy * Wd + xx);
        e.y = *reinterpret_cast<const unsigned int*>(&w);
        s_tap[i] = e;
    }
    __syncthreads();

    const int q  = tid & 31;
    const int bs = tid >> 5;
    const uint4* base16 = reinterpret_cast<const uint4*>(fbase) + q;
    float* outm = out + (size_t)m * (NBINS * CCH);

    for (int bb = bs; bb < bcnt; bb += 8) {
        const int tb = bb * 16;
        float2 facc[4] = {{0.f,0.f},{0.f,0.f},{0.f,0.f},{0.f,0.f}};
#pragma unroll
        for (int smp = 0; smp < 4; ++smp) {
            __half2 hacc[4];
#pragma unroll
            for (int t = 0; t < 4; ++t) {
                const uint2 e = s_tap[tb + smp * 4 + t];   // LDS.64 broadcast
                const __half2 w = *reinterpret_cast<const __half2*>(&e.y);
                const uint4 u = __ldg(base16 + (size_t)e.x * 32);
                const __half2* h = reinterpret_cast<const __half2*>(&u);
#pragma unroll
                for (int j = 0; j < 4; ++j)
                    hacc[j] = (t == 0) ? __hmul2(h[j], w)
                                       : __hfma2(h[j], w, hacc[j]);
            }
#pragma unroll
            for (int j = 0; j < 4; ++j) {
                const float2 f = __half22float2(hacc[j]);
                facc[j].x += f.x;
                facc[j].y += f.y;
            }
        }
        // stage as fp16: 8 halves (uint4) per lane, one STS.128
        uint4 pk;
        {
            const __half2 p0 = __floats2half2_rn(facc[0].x, facc[0].y);
            const __half2 p1 = __floats2half2_rn(facc[1].x, facc[1].y);
            const __half2 p2 = __floats2half2_rn(facc[2].x, facc[2].y);
            const __half2 p3 = __floats2half2_rn(facc[3].x, facc[3].y);
            pk.x = *reinterpret_cast<const unsigned int*>(&p0);
            pk.y = *reinterpret_cast<const unsigned int*>(&p1);
            pk.z = *reinterpret_cast<const unsigned int*>(&p2);
            pk.w = *reinterpret_cast<const unsigned int*>(&p3);
        }
        *reinterpret_cast<uint4*>(s_out + bb * SPITCH_H + q * 8) = pk;
    }
    __syncthreads();

    // Transposed dump: compile-time bin counts (magic-multiply div).
    if (phase == 0) {
        for (int i = tid; i < 25 * CCH; i += 256) {
            const int c  = i / 25;
            const int bb = i - c * 25;
            outm[c * NBINS + bb] = __half2float(s_out[bb * SPITCH_H + c]);
        }
    } else {
        for (int i = tid; i < 24 * CCH; i += 256) {
            const int c  = i / 24;
            const int bb = i - c * 24;
            outm[c * NBINS + 25 + bb] = __half2float(s_out[bb * SPITCH_H + c]);
        }
    }
}

// ---------------------------------------------------------------------------
extern "C" void kernel_launch(void* const* d_in, const int* in_sizes, int n_in,
                              void* d_out, int out_size)
{
    const float* f0    = (const float*)d_in[0];
    const float* f1    = (const float*)d_in[1];
    const float* f2    = (const float*)d_in[2];
    const float* f3    = (const float*)d_in[3];
    const float* boxes = (const float*)d_in[4];
    float*       out   = (float*)d_out;

    const int M = in_sizes[4] / 4;   // 1024 boxes
    const int R = M / NIMG;          // 512 per image

    transpose_fused<<<dim3(680, CCH / 32, NIMG), dim3(8, 32)>>>(f0, f1, f2, f3);
    roi_pool_kernel<<<M * 2, 256>>>(boxes, out, R);
}